// round 5
// baseline (speedup 1.0000x reference)
#include <cuda_runtime.h>
#include <cuda_fp16.h>
#include <mma.h>
#include <cstdint>

using namespace nvcuda;

// Fused 2-layer GCN (chain graph), wmma fp16 3-term split.
// Round-5 structure:
//  - prep kernel splits W1/W2 -> fp16 hi/lo __device__ globals (once/launch);
//    main kernel loads B fragments directly from global (L1/L2 shared).
//  - biases folded into MMA via ones-matrix x bias-rows trick (hi+lo exact).
//  - MMA2 accumulators store directly to global out (full tiles).
//  - smem ~65KB -> 3 CTAs/SM target.

#define NTHREADS 256
#define OUT_TILE 64
#define MROWS    80

#define LDA  72     // fp16: A1 [80][64], A2c [64][64]
#define LDH  132    // fp32: sH [80][128]
#define LDX  68     // fp32: sXs [69][64]
#define LDO  68     // fp32: sOut (edge fallback) [64][64]

#define OFF_A1H  0            // 80*72*2 = 11520
#define OFF_A1L  11520
#define OFF_A2H  0            // [64][72] overlays A1 (dead after MMA1)
#define OFF_A2L  11520
#define OFF_SH   23040        // 80*132*4 = 42240 ; sXs/sOut overlay
#define OFF_ONES 65280        // 16*16 fp16 = 512
#define OFF_SDV  65792        // 72 floats = 288
#define SMEM_BYTES 66080

__device__ __align__(256) __half g_W1h[64 * 128];
__device__ __align__(256) __half g_W1l[64 * 128];
__device__ __align__(256) __half g_W2h[128 * 64];
__device__ __align__(256) __half g_W2l[128 * 64];
__device__ __align__(256) __half g_Bb1[16 * 128];   // rows 0/1 = hi/lo(b1)
__device__ __align__(256) __half g_Bb2[16 * 64];    // rows 0/1 = hi/lo(b2)

__device__ __forceinline__ void split_h(float v, __half& hi, __half& lo) {
    hi = __float2half_rn(v);
    lo = __float2half_rn(v - __half2float(hi));
}

__global__ void gcn_prep(const float* __restrict__ W1,
                         const float* __restrict__ b1,
                         const float* __restrict__ W2,
                         const float* __restrict__ b2)
{
    int tid = blockIdx.x * blockDim.x + threadIdx.x;
    int nt = gridDim.x * blockDim.x;
    for (int e = tid; e < 64 * 128; e += nt) {
        __half hi, lo; split_h(W1[e], hi, lo);
        g_W1h[e] = hi; g_W1l[e] = lo;
    }
    for (int e = tid; e < 128 * 64; e += nt) {
        __half hi, lo; split_h(W2[e], hi, lo);
        g_W2h[e] = hi; g_W2l[e] = lo;
    }
    for (int e = tid; e < 16 * 128; e += nt) {
        int r = e >> 7, c = e & 127;
        __half hi, lo; split_h(b1[c], hi, lo);
        g_Bb1[e] = (r == 0) ? hi : (r == 1) ? lo : __float2half_rn(0.f);
    }
    for (int e = tid; e < 16 * 64; e += nt) {
        int r = e >> 6, c = e & 63;
        __half hi, lo; split_h(b2[c], hi, lo);
        g_Bb2[e] = (r == 0) ? hi : (r == 1) ? lo : __float2half_rn(0.f);
    }
}

__global__ __launch_bounds__(NTHREADS, 3)
void gcn_main(const float* __restrict__ x, float* __restrict__ out, int N)
{
    extern __shared__ char smem[];
    const int tid = threadIdx.x, wid = tid >> 5;
    const long long base = (long long)blockIdx.x * OUT_TILE;

    float* sdv  = (float*)(smem + OFF_SDV);   // t -> node base-2+t, t<69
    float* sXs  = (float*)(smem + OFF_SH);    // [69][LDX]
    float* sH   = (float*)(smem + OFF_SH);    // [80][LDH]
    float* sOut = (float*)(smem + OFF_SH);    // edge fallback
    __half* sOnes = (__half*)(smem + OFF_ONES);
    __half* A1h = (__half*)(smem + OFF_A1H);
    __half* A1l = (__half*)(smem + OFF_A1L);
    __half* A2h = (__half*)(smem + OFF_A2H);
    __half* A2l = (__half*)(smem + OFF_A2L);

    // ---------- P1: stage dinv / ones / x ----------
    if (tid < 72) {
        long long node = base - 2 + tid;
        float v = 0.0f;
        if (tid < 69 && node >= 0 && node < (long long)N)
            v = (node == 0 || node == (long long)N - 1)
                ? 0.70710678118654752f : 0.57735026918962576f;
        sdv[tid] = v;
    }
    // A_ones: 16x16, cols 0 and 1 = 1.0 (picks bias hi+lo rows of B_bias)
    sOnes[tid] = __float2half_rn(((tid & 15) < 2) ? 1.0f : 0.0f);

    for (int e = tid; e < 69 * 16; e += NTHREADS) {
        int t = e / 16, q = e & 15;
        long long node = base - 2 + t;
        float4 v = make_float4(0.f, 0.f, 0.f, 0.f);
        if (node >= 0 && node < (long long)N)
            v = *(const float4*)(x + node * 64 + q * 4);
        *(float4*)&sXs[t * LDX + q * 4] = v;
    }
    __syncthreads();

    // ---------- P2: stencil1 + split -> A1 [80][64] ----------
    for (int e = tid; e < MROWS * 64; e += NTHREADS) {
        int j = e >> 6, k = e & 63;
        float a = 0.0f;
        if (j <= 66) {
            float d0 = sdv[j], d1 = sdv[j + 1], d2 = sdv[j + 2];
            a = d1 * (d0 * sXs[j * LDX + k] +
                      d1 * sXs[(j + 1) * LDX + k] +
                      d2 * sXs[(j + 2) * LDX + k]);
        }
        __half hi, lo;
        split_h(a, hi, lo);
        A1h[j * LDA + k] = hi;
        A1l[j * LDA + k] = lo;
    }
    __syncthreads();

    // ---------- P3: MMA1  sH[80][128] = A1 @ W1split + b1 ----------
    // warp w: colslab w (16 cols), rowslabs 0..4. B frags from GLOBAL.
    {
        wmma::fragment<wmma::matrix_a, 16, 16, 16, __half, wmma::row_major> ah, al;
        wmma::fragment<wmma::matrix_b, 16, 16, 16, __half, wmma::row_major> bh, bl;
        wmma::fragment<wmma::accumulator, 16, 16, 16, float> acc[5];
        #pragma unroll
        for (int r = 0; r < 5; r++) wmma::fill_fragment(acc[r], 0.0f);

        // bias init: acc[r] += ones2 @ Bb1 (rows 0/1 = hi/lo of b1)
        wmma::load_matrix_sync(ah, sOnes, 16);
        wmma::load_matrix_sync(bh, g_Bb1 + wid * 16, 128);
        #pragma unroll
        for (int r = 0; r < 5; r++) wmma::mma_sync(acc[r], ah, bh, acc[r]);

        #pragma unroll
        for (int k = 0; k < 4; k++) {
            wmma::load_matrix_sync(bh, g_W1h + (k * 16) * 128 + wid * 16, 128);
            wmma::load_matrix_sync(bl, g_W1l + (k * 16) * 128 + wid * 16, 128);
            #pragma unroll
            for (int r = 0; r < 5; r++) {
                wmma::load_matrix_sync(ah, A1h + (r * 16) * LDA + k * 16, LDA);
                wmma::load_matrix_sync(al, A1l + (r * 16) * LDA + k * 16, LDA);
                wmma::mma_sync(acc[r], ah, bh, acc[r]);
                wmma::mma_sync(acc[r], ah, bl, acc[r]);
                wmma::mma_sync(acc[r], al, bh, acc[r]);
            }
        }
        #pragma unroll
        for (int r = 0; r < 5; r++)
            wmma::store_matrix_sync(sH + (r * 16) * LDH + wid * 16, acc[r],
                                    LDH, wmma::mem_row_major);
    }
    __syncthreads();   // sH ready; A1 reads done (A2 may overlay)

    // ---------- P4: K-chunked stencil2 + MMA2 ----------
    // warp w: colslab c2=(w&3)*16, rowslabs rs0=(w>>2)*2, rs0+1
    wmma::fragment<wmma::accumulator, 16, 16, 16, float> acc2[2];
    wmma::fill_fragment(acc2[0], 0.0f);
    wmma::fill_fragment(acc2[1], 0.0f);
    const int c2 = (wid & 3) * 16, rs0 = (wid >> 2) * 2;
    {   // bias init
        wmma::fragment<wmma::matrix_a, 16, 16, 16, __half, wmma::row_major> aon;
        wmma::fragment<wmma::matrix_b, 16, 16, 16, __half, wmma::row_major> bb;
        wmma::load_matrix_sync(aon, sOnes, 16);
        wmma::load_matrix_sync(bb, g_Bb2 + c2, 64);
        wmma::mma_sync(acc2[0], aon, bb, acc2[0]);
        wmma::mma_sync(acc2[1], aon, bb, acc2[1]);
    }

    #pragma unroll
    for (int kc = 0; kc < 128; kc += 64) {
        // stencil2: z[r][kk] over relu(sH) (bias already inside sH)
        for (int e = tid; e < 64 * 64; e += NTHREADS) {
            int r = e >> 6, k = kc + (e & 63);
            float h0 = fmaxf(sH[ r      * LDH + k], 0.0f);
            float h1 = fmaxf(sH[(r + 1) * LDH + k], 0.0f);
            float h2 = fmaxf(sH[(r + 2) * LDH + k], 0.0f);
            float z = sdv[r + 2] * (sdv[r + 1] * h0 + sdv[r + 2] * h1 +
                                    sdv[r + 3] * h2);
            __half hi, lo;
            split_h(z, hi, lo);
            A2h[r * LDA + (e & 63)] = hi;
            A2l[r * LDA + (e & 63)] = lo;
        }
        __syncthreads();

        {
            wmma::fragment<wmma::matrix_a, 16, 16, 16, __half, wmma::row_major> ah, al;
            wmma::fragment<wmma::matrix_b, 16, 16, 16, __half, wmma::row_major> bh, bl;
            #pragma unroll
            for (int kk = 0; kk < 4; kk++) {
                wmma::load_matrix_sync(bh, g_W2h + (kc + kk * 16) * 64 + c2, 64);
                wmma::load_matrix_sync(bl, g_W2l + (kc + kk * 16) * 64 + c2, 64);
                #pragma unroll
                for (int r = 0; r < 2; r++) {
                    wmma::load_matrix_sync(ah, A2h + ((rs0 + r) * 16) * LDA + kk * 16, LDA);
                    wmma::load_matrix_sync(al, A2l + ((rs0 + r) * 16) * LDA + kk * 16, LDA);
                    wmma::mma_sync(acc2[r], ah, bh, acc2[r]);
                    wmma::mma_sync(acc2[r], ah, bl, acc2[r]);
                    wmma::mma_sync(acc2[r], al, bh, acc2[r]);
                }
            }
        }
        __syncthreads();
    }

    // ---------- P5: store ----------
    if (base + OUT_TILE <= (long long)N) {
        // full tile: fragments straight to global (bias already inside)
        wmma::store_matrix_sync(out + (base + rs0 * 16) * 64 + c2, acc2[0],
                                64, wmma::mem_row_major);
        wmma::store_matrix_sync(out + (base + rs0 * 16 + 16) * 64 + c2, acc2[1],
                                64, wmma::mem_row_major);
    } else {
        // edge tile: stage in smem (sH dead), guarded copy
        wmma::store_matrix_sync(sOut + (rs0 * 16) * LDO + c2, acc2[0], LDO,
                                wmma::mem_row_major);
        wmma::store_matrix_sync(sOut + (rs0 * 16 + 16) * LDO + c2, acc2[1], LDO,
                                wmma::mem_row_major);
        __syncthreads();
        for (int e = tid; e < OUT_TILE * 16; e += NTHREADS) {
            int r = e >> 4, q = e & 15;
            long long node = base + r;
            if (node < (long long)N)
                *(float4*)(out + node * 64 + q * 4) =
                    *(float4*)&sOut[r * LDO + q * 4];
        }
    }
}

extern "C" void kernel_launch(void* const* d_in, const int* in_sizes, int n_in,
                              void* d_out, int out_size)
{
    const float* x  = (const float*)d_in[0];
    const float* W1 = (const float*)d_in[2];
    const float* b1 = (const float*)d_in[3];
    const float* W2 = (const float*)d_in[4];
    const float* b2 = (const float*)d_in[5];
    float* out = (float*)d_out;

    int N = in_sizes[0] / 64;
    int nblocks = (N + OUT_TILE - 1) / OUT_TILE;

    gcn_prep<<<32, 256>>>(W1, b1, W2, b2);

    cudaFuncSetAttribute(gcn_main,
                         cudaFuncAttributeMaxDynamicSharedMemorySize,
                         SMEM_BYTES);
    gcn_main<<<nblocks, NTHREADS, SMEM_BYTES>>>(x, out, N);
}

// round 6
// speedup vs baseline: 1.4424x; 1.4424x over previous
#include <cuda_runtime.h>
#include <cuda_fp16.h>
#include <mma.h>
#include <cstdint>

using namespace nvcuda;

// Fused 2-layer GCN (chain graph), wmma fp16 3-term split, 2 CTAs/SM.
// R6: pre-split weights (prep kernel) staged to smem via uint4;
//     MMA1 4x2 warp split (A redundancy 8->4); 2-row stencils (float2);
//     relu in MMA1 fragment epilogue; bias folded via ones-trick;
//     direct fragment->global store.

#define NTHREADS 256
#define OUT_TILE 64
#define MROWS    80

#define LDA  72     // fp16: A1 [80][72], A2c [64][72]
#define LDW1 136    // fp16: W1 [64][136]
#define LDW2 72     // fp16: W2 [128][72]
#define LDH  132    // fp32: sH [80][132]
#define LDX  68     // fp32: sXs [69][68]
#define LDO  68     // fp32: edge fallback

#define OFF_A1H 0             // 80*72*2 = 11520
#define OFF_A1L 11520
#define OFF_A2H 0             // overlays A1 after MMA1
#define OFF_A2L 9216          // 64*72*2
#define OFF_W   23040
#define OFF_W1H OFF_W                 // 64*136*2 = 17408
#define OFF_W1L (OFF_W + 17408)
#define OFF_W2H OFF_W                 // 128*72*2 = 18432 (after MMA1)
#define OFF_W2L (OFF_W + 18432)
#define OFF_SH  59904         // 80*132*4 = 42240 ; sXs/sOut overlay
#define OFF_ONES 102144       // 16*16 fp16 = 512
#define OFF_SDV  102656       // 72 floats = 288
#define SMEM_BYTES 102944

__device__ __align__(256) __half g_W1h[64 * 128];
__device__ __align__(256) __half g_W1l[64 * 128];
__device__ __align__(256) __half g_W2h[128 * 64];
__device__ __align__(256) __half g_W2l[128 * 64];
__device__ __align__(256) __half g_Bb1[16 * 128];   // rows 0/1 = hi/lo(b1)
__device__ __align__(256) __half g_Bb2[16 * 64];    // rows 0/1 = hi/lo(b2)

__device__ __forceinline__ void split_h(float v, __half& hi, __half& lo) {
    hi = __float2half_rn(v);
    lo = __float2half_rn(v - __half2float(hi));
}

__global__ void gcn_prep(const float* __restrict__ W1,
                         const float* __restrict__ b1,
                         const float* __restrict__ W2,
                         const float* __restrict__ b2)
{
    int tid = blockIdx.x * blockDim.x + threadIdx.x;
    int nt = gridDim.x * blockDim.x;
    for (int e = tid; e < 64 * 128; e += nt) {
        __half hi, lo; split_h(W1[e], hi, lo);
        g_W1h[e] = hi; g_W1l[e] = lo;
    }
    for (int e = tid; e < 128 * 64; e += nt) {
        __half hi, lo; split_h(W2[e], hi, lo);
        g_W2h[e] = hi; g_W2l[e] = lo;
    }
    for (int e = tid; e < 16 * 128; e += nt) {
        int r = e >> 7, c = e & 127;
        __half hi, lo; split_h(b1[c], hi, lo);
        g_Bb1[e] = (r == 0) ? hi : (r == 1) ? lo : __float2half_rn(0.f);
    }
    for (int e = tid; e < 16 * 64; e += nt) {
        int r = e >> 6, c = e & 63;
        __half hi, lo; split_h(b2[c], hi, lo);
        g_Bb2[e] = (r == 0) ? hi : (r == 1) ? lo : __float2half_rn(0.f);
    }
}

__global__ __launch_bounds__(NTHREADS, 2)
void gcn_main(const float* __restrict__ x, float* __restrict__ out, int N)
{
    extern __shared__ char smem[];
    const int tid = threadIdx.x, wid = tid >> 5;
    const long long base = (long long)blockIdx.x * OUT_TILE;

    float* sdv  = (float*)(smem + OFF_SDV);   // t -> node base-2+t (t<69 valid)
    float* sXs  = (float*)(smem + OFF_SH);    // [69][LDX]
    float* sH   = (float*)(smem + OFF_SH);    // [80][LDH]
    float* sOut = (float*)(smem + OFF_SH);
    __half* sOnes = (__half*)(smem + OFF_ONES);
    __half* A1h = (__half*)(smem + OFF_A1H);
    __half* A1l = (__half*)(smem + OFF_A1L);
    __half* A2h = (__half*)(smem + OFF_A2H);
    __half* A2l = (__half*)(smem + OFF_A2L);
    __half* W1h = (__half*)(smem + OFF_W1H);
    __half* W1l = (__half*)(smem + OFF_W1L);
    __half* W2h = (__half*)(smem + OFF_W2H);
    __half* W2l = (__half*)(smem + OFF_W2L);

    // ---------- P1: stage dinv / ones / x / W1 pair ----------
    if (tid < 72) {
        long long node = base - 2 + tid;
        float v = 0.0f;
        if (tid < 69 && node >= 0 && node < (long long)N)
            v = (node == 0 || node == (long long)N - 1)
                ? 0.70710678118654752f : 0.57735026918962576f;
        sdv[tid] = v;
    }
    sOnes[tid] = __float2half_rn(((tid & 15) < 2) ? 1.0f : 0.0f);

    for (int e = tid; e < 64 * 16; e += NTHREADS) {   // W1 pair: 16 uint4/row
        int r = e >> 4, q = e & 15;
        *(uint4*)&W1h[r * LDW1 + q * 8] = ((const uint4*)g_W1h)[e];
        *(uint4*)&W1l[r * LDW1 + q * 8] = ((const uint4*)g_W1l)[e];
    }
    for (int e = tid; e < 69 * 16; e += NTHREADS) {   // x rows base-2..base+66
        int t = e / 16, q = e & 15;
        long long node = base - 2 + t;
        float4 v = make_float4(0.f, 0.f, 0.f, 0.f);
        if (node >= 0 && node < (long long)N)
            v = *(const float4*)(x + node * 64 + q * 4);
        *(float4*)&sXs[t * LDX + q * 4] = v;
    }
    __syncthreads();

    // ---------- P2: stencil1 (2 rows/thread, float2) -> A1 [80][64] ----------
    // task: row pair (2*rp, 2*rp+1), k pair. valid h rows j<=66.
    for (int e = tid; e < 40 * 32; e += NTHREADS) {
        int rp = e >> 5, kp = (e & 31) * 2;
        int j0 = rp * 2;
        float2 v0 = make_float2(0.f, 0.f), v1 = v0, v2 = v0, v3 = v0;
        if (j0     <= 68) v0 = *(float2*)&sXs[ j0      * LDX + kp];
        if (j0 + 1 <= 68) v1 = *(float2*)&sXs[(j0 + 1) * LDX + kp];
        if (j0 + 2 <= 68) v2 = *(float2*)&sXs[(j0 + 2) * LDX + kp];
        if (j0 + 3 <= 68) v3 = *(float2*)&sXs[(j0 + 3) * LDX + kp];
        #pragma unroll
        for (int rr = 0; rr < 2; rr++) {
            int j = j0 + rr;
            float ax = 0.f, ay = 0.f;
            if (j <= 66) {
                float d0 = sdv[j], d1 = sdv[j + 1], d2 = sdv[j + 2];
                float2 u0 = rr ? v1 : v0, u1 = rr ? v2 : v1, u2 = rr ? v3 : v2;
                ax = d1 * (d0 * u0.x + d1 * u1.x + d2 * u2.x);
                ay = d1 * (d0 * u0.y + d1 * u1.y + d2 * u2.y);
            }
            __half hx, lx, hy, ly;
            split_h(ax, hx, lx);
            split_h(ay, hy, ly);
            *(__half2*)&A1h[j * LDA + kp] = __halves2half2(hx, hy);
            *(__half2*)&A1l[j * LDA + kp] = __halves2half2(lx, ly);
        }
    }
    __syncthreads();

    // ---------- P3: MMA1  sH = relu(A1 @ W1 + b1) ----------
    // 4 colgroups (32 cols) x 2 rowgroups (slabs {0,1,2} / {3,4})
    {
        const int cg = wid & 3, rg = wid >> 2;
        const int nr = rg ? 2 : 3, s0 = rg * 3;
        wmma::fragment<wmma::matrix_a, 16, 16, 16, __half, wmma::row_major> ah, al;
        wmma::fragment<wmma::matrix_b, 16, 16, 16, __half, wmma::row_major> bh[2], bl[2];
        wmma::fragment<wmma::accumulator, 16, 16, 16, float> acc[3][2];
        #pragma unroll
        for (int r = 0; r < 3; r++)
            #pragma unroll
            for (int c = 0; c < 2; c++) wmma::fill_fragment(acc[r][c], 0.0f);

        // bias init
        wmma::load_matrix_sync(ah, sOnes, 16);
        #pragma unroll
        for (int c = 0; c < 2; c++)
            wmma::load_matrix_sync(bh[c], g_Bb1 + (cg * 2 + c) * 16, 128);
        #pragma unroll
        for (int r = 0; r < 3; r++)
            if (r < nr)
                #pragma unroll
                for (int c = 0; c < 2; c++)
                    wmma::mma_sync(acc[r][c], ah, bh[c], acc[r][c]);

        #pragma unroll
        for (int k = 0; k < 4; k++) {
            #pragma unroll
            for (int c = 0; c < 2; c++) {
                wmma::load_matrix_sync(bh[c], W1h + (k * 16) * LDW1 + (cg * 2 + c) * 16, LDW1);
                wmma::load_matrix_sync(bl[c], W1l + (k * 16) * LDW1 + (cg * 2 + c) * 16, LDW1);
            }
            #pragma unroll
            for (int r = 0; r < 3; r++)
                if (r < nr) {
                    int s = s0 + r;
                    wmma::load_matrix_sync(ah, A1h + (s * 16) * LDA + k * 16, LDA);
                    wmma::load_matrix_sync(al, A1l + (s * 16) * LDA + k * 16, LDA);
                    #pragma unroll
                    for (int c = 0; c < 2; c++) {
                        wmma::mma_sync(acc[r][c], ah, bh[c], acc[r][c]);
                        wmma::mma_sync(acc[r][c], ah, bl[c], acc[r][c]);
                        wmma::mma_sync(acc[r][c], al, bh[c], acc[r][c]);
                    }
                }
        }
        // relu in fragment, then store
        #pragma unroll
        for (int r = 0; r < 3; r++)
            if (r < nr)
                #pragma unroll
                for (int c = 0; c < 2; c++) {
                    #pragma unroll
                    for (int i = 0; i < acc[r][c].num_elements; i++)
                        acc[r][c].x[i] = fmaxf(acc[r][c].x[i], 0.0f);
                    wmma::store_matrix_sync(
                        sH + ((s0 + r) * 16) * LDH + (cg * 2 + c) * 16,
                        acc[r][c], LDH, wmma::mem_row_major);
                }
    }
    __syncthreads();   // sH ready; A1 + W1 dead

    // ---------- P4: W2 pair stage + K-chunked stencil2 / MMA2 ----------
    for (int e = tid; e < 128 * 8; e += NTHREADS) {   // W2 pair: 8 uint4/row
        int r = e >> 3, q = e & 7;
        *(uint4*)&W2h[r * LDW2 + q * 8] = ((const uint4*)g_W2h)[e];
        *(uint4*)&W2l[r * LDW2 + q * 8] = ((const uint4*)g_W2l)[e];
    }

    wmma::fragment<wmma::accumulator, 16, 16, 16, float> acc2[2];
    wmma::fill_fragment(acc2[0], 0.0f);
    wmma::fill_fragment(acc2[1], 0.0f);
    const int c2 = (wid & 3) * 16, rs0 = (wid >> 2) * 2;
    {   // bias init
        wmma::fragment<wmma::matrix_a, 16, 16, 16, __half, wmma::row_major> aon;
        wmma::fragment<wmma::matrix_b, 16, 16, 16, __half, wmma::row_major> bb;
        wmma::load_matrix_sync(aon, sOnes, 16);
        wmma::load_matrix_sync(bb, g_Bb2 + c2, 64);
        wmma::mma_sync(acc2[0], aon, bb, acc2[0]);
        wmma::mma_sync(acc2[1], aon, bb, acc2[1]);
    }

    #pragma unroll
    for (int kc = 0; kc < 128; kc += 64) {
        // stencil2: 2 rows/thread, float2 along k (sH holds relu(H) already)
        for (int e = tid; e < 32 * 32; e += NTHREADS) {
            int rp = e >> 5, kk = (e & 31) * 2;
            int r0 = rp * 2, k = kc + kk;
            float2 h0 = *(float2*)&sH[ r0      * LDH + k];
            float2 h1 = *(float2*)&sH[(r0 + 1) * LDH + k];
            float2 h2 = *(float2*)&sH[(r0 + 2) * LDH + k];
            float2 h3 = *(float2*)&sH[(r0 + 3) * LDH + k];
            #pragma unroll
            for (int rr = 0; rr < 2; rr++) {
                int r = r0 + rr;
                float d1 = sdv[r + 1], d2 = sdv[r + 2], d3 = sdv[r + 3];
                float2 u0 = rr ? h1 : h0, u1 = rr ? h2 : h1, u2 = rr ? h3 : h2;
                float zx = d2 * (d1 * u0.x + d2 * u1.x + d3 * u2.x);
                float zy = d2 * (d1 * u0.y + d2 * u1.y + d3 * u2.y);
                __half hx, lx, hy, ly;
                split_h(zx, hx, lx);
                split_h(zy, hy, ly);
                *(__half2*)&A2h[r * LDA + kk] = __halves2half2(hx, hy);
                *(__half2*)&A2l[r * LDA + kk] = __halves2half2(lx, ly);
            }
        }
        __syncthreads();   // A2 chunk + (iter0) W2 ready

        {
            wmma::fragment<wmma::matrix_a, 16, 16, 16, __half, wmma::row_major> ah, al;
            wmma::fragment<wmma::matrix_b, 16, 16, 16, __half, wmma::row_major> bh, bl;
            #pragma unroll
            for (int kk = 0; kk < 4; kk++) {
                wmma::load_matrix_sync(bh, W2h + (kc + kk * 16) * LDW2 + c2, LDW2);
                wmma::load_matrix_sync(bl, W2l + (kc + kk * 16) * LDW2 + c2, LDW2);
                #pragma unroll
                for (int r = 0; r < 2; r++) {
                    wmma::load_matrix_sync(ah, A2h + ((rs0 + r) * 16) * LDA + kk * 16, LDA);
                    wmma::load_matrix_sync(al, A2l + ((rs0 + r) * 16) * LDA + kk * 16, LDA);
                    wmma::mma_sync(acc2[r], ah, bh, acc2[r]);
                    wmma::mma_sync(acc2[r], ah, bl, acc2[r]);
                    wmma::mma_sync(acc2[r], al, bh, acc2[r]);
                }
            }
        }
        __syncthreads();   // A2/sH reads done before next chunk / store reuse
    }

    // ---------- P5: store (bias already inside accumulators) ----------
    if (base + OUT_TILE <= (long long)N) {
        wmma::store_matrix_sync(out + (base + rs0 * 16) * 64 + c2, acc2[0],
                                64, wmma::mem_row_major);
        wmma::store_matrix_sync(out + (base + rs0 * 16 + 16) * 64 + c2, acc2[1],
                                64, wmma::mem_row_major);
    } else {
        wmma::store_matrix_sync(sOut + (rs0 * 16) * LDO + c2, acc2[0], LDO,
                                wmma::mem_row_major);
        wmma::store_matrix_sync(sOut + (rs0 * 16 + 16) * LDO + c2, acc2[1], LDO,
                                wmma::mem_row_major);
        __syncthreads();
        for (int e = tid; e < OUT_TILE * 16; e += NTHREADS) {
            int r = e >> 4, q = e & 15;
            long long node = base + r;
            if (node < (long long)N)
                *(float4*)(out + node * 64 + q * 4) =
                    *(float4*)&sOut[r * LDO + q * 4];
        }
    }
}

extern "C" void kernel_launch(void* const* d_in, const int* in_sizes, int n_in,
                              void* d_out, int out_size)
{
    const float* x  = (const float*)d_in[0];
    const float* W1 = (const float*)d_in[2];
    const float* b1 = (const float*)d_in[3];
    const float* W2 = (const float*)d_in[4];
    const float* b2 = (const float*)d_in[5];
    float* out = (float*)d_out;

    int N = in_sizes[0] / 64;
    int nblocks = (N + OUT_TILE - 1) / OUT_TILE;

    gcn_prep<<<32, 256>>>(W1, b1, W2, b2);

    cudaFuncSetAttribute(gcn_main,
                         cudaFuncAttributeMaxDynamicSharedMemorySize,
                         SMEM_BYTES);
    gcn_main<<<nblocks, NTHREADS, SMEM_BYTES>>>(x, out, N);
}

// round 7
// speedup vs baseline: 1.8197x; 1.2616x over previous
#include <cuda_runtime.h>
#include <cuda_fp16.h>
#include <mma.h>
#include <cstdint>

using namespace nvcuda;

// Fused 2-layer GCN (chain graph), wmma fp16 3-term split, 2 CTAs/SM.
// R7: cp.async staging (flat 16B copies from pre-padded split weights),
//     W1 copy overlapped with stencil1, W2 copy overlapped with stencil2,
//     bias matrices staged to smem, 6 barriers/tile.

#define NTHREADS 256
#define OUT_TILE 64
#define MROWS    80

#define LDA  72     // fp16: A1 [80][72], A2c [64][72]
#define LDW1 136    // fp16: W1 [64][136]  (prep pre-pads)
#define LDW2 72     // fp16: W2 [128][72]  (prep pre-pads)
#define LDH  132    // fp32: sH [80][132]
#define LDX  68     // fp32: sXs [69][68]  (row = 272B, 16B-aligned)
#define LDO  68

#define OFF_A1H 0             // 80*72*2 = 11520
#define OFF_A1L 11520         // A1 region ends 23040
#define OFF_A2H 0             // A2c [64][72] overlays A1 after MMA1
#define OFF_A2L 9216
#define OFF_W   23040
#define OFF_W1H OFF_W                 // 64*136*2 = 17408
#define OFF_W1L (OFF_W + 17408)       // W1 ends 57856
#define OFF_W2H OFF_W                 // 128*72*2 = 18432 (overlays W1)
#define OFF_W2L (OFF_W + 18432)       // W2 ends 59904
#define OFF_SH  59904         // 80*132*4 = 42240 ; sXs/sOut overlay; ends 102144
#define OFF_ONES 102144       // 16*16 fp16 = 512
#define OFF_BB1  102656       // 16*128 fp16 = 4096
#define OFF_BB2  106752       // 16*64 fp16 = 2048
#define OFF_SDV  108800       // 72 floats = 288
#define SMEM_BYTES 109088     // x2 CTAs = 218176 <= 228KB/SM

__device__ __align__(256) __half g_W1ph[64 * 136];   // pre-padded hi
__device__ __align__(256) __half g_W1pl[64 * 136];   // pre-padded lo
__device__ __align__(256) __half g_W2ph[128 * 72];
__device__ __align__(256) __half g_W2pl[128 * 72];
__device__ __align__(256) __half g_Bb1[16 * 128];    // rows 0/1 = hi/lo(b1)
__device__ __align__(256) __half g_Bb2[16 * 64];

__device__ __forceinline__ void split_h(float v, __half& hi, __half& lo) {
    hi = __float2half_rn(v);
    lo = __float2half_rn(v - __half2float(hi));
}
__device__ __forceinline__ uint32_t smem_u32(const void* p) {
    uint32_t a;
    asm("{ .reg .u64 t; cvta.to.shared.u64 t, %1; cvt.u32.u64 %0, t; }"
        : "=r"(a) : "l"(p));
    return a;
}
#define CP16(dst, src, nbytes) \
    asm volatile("cp.async.cg.shared.global [%0], [%1], 16, %2;" \
                 :: "r"(dst), "l"(src), "r"((uint32_t)(nbytes)))
#define CP_COMMIT() asm volatile("cp.async.commit_group;")
#define CP_WAIT(n)  asm volatile("cp.async.wait_group %0;" :: "n"(n))

__global__ void gcn_prep(const float* __restrict__ W1,
                         const float* __restrict__ b1,
                         const float* __restrict__ W2,
                         const float* __restrict__ b2)
{
    int tid = blockIdx.x * blockDim.x + threadIdx.x;
    int nt = gridDim.x * blockDim.x;
    for (int e = tid; e < 64 * 136; e += nt) {
        int r = e / 136, c = e % 136;
        __half hi = __float2half_rn(0.f), lo = hi;
        if (c < 128) split_h(W1[r * 128 + c], hi, lo);
        g_W1ph[e] = hi; g_W1pl[e] = lo;
    }
    for (int e = tid; e < 128 * 72; e += nt) {
        int r = e / 72, c = e % 72;
        __half hi = __float2half_rn(0.f), lo = hi;
        if (c < 64) split_h(W2[r * 64 + c], hi, lo);
        g_W2ph[e] = hi; g_W2pl[e] = lo;
    }
    for (int e = tid; e < 16 * 128; e += nt) {
        int r = e >> 7, c = e & 127;
        __half hi, lo; split_h(b1[c], hi, lo);
        g_Bb1[e] = (r == 0) ? hi : (r == 1) ? lo : __float2half_rn(0.f);
    }
    for (int e = tid; e < 16 * 64; e += nt) {
        int r = e >> 6, c = e & 63;
        __half hi, lo; split_h(b2[c], hi, lo);
        g_Bb2[e] = (r == 0) ? hi : (r == 1) ? lo : __float2half_rn(0.f);
    }
}

__global__ __launch_bounds__(NTHREADS, 2)
void gcn_main(const float* __restrict__ x, float* __restrict__ out, int N)
{
    extern __shared__ char smem[];
    const uint32_t sb = smem_u32(smem);
    const int tid = threadIdx.x, wid = tid >> 5;
    const long long base = (long long)blockIdx.x * OUT_TILE;

    float* sdv  = (float*)(smem + OFF_SDV);
    float* sXs  = (float*)(smem + OFF_SH);
    float* sH   = (float*)(smem + OFF_SH);
    float* sOut = (float*)(smem + OFF_SH);
    __half* sOnes = (__half*)(smem + OFF_ONES);
    __half* sBb1  = (__half*)(smem + OFF_BB1);
    __half* sBb2  = (__half*)(smem + OFF_BB2);
    __half* A1h = (__half*)(smem + OFF_A1H);
    __half* A1l = (__half*)(smem + OFF_A1L);
    __half* A2h = (__half*)(smem + OFF_A2H);
    __half* A2l = (__half*)(smem + OFF_A2L);
    __half* W1h = (__half*)(smem + OFF_W1H);
    __half* W1l = (__half*)(smem + OFF_W1L);
    __half* W2h = (__half*)(smem + OFF_W2H);
    __half* W2l = (__half*)(smem + OFF_W2L);

    // ---------- P1: async stage x (group0), W1+biases (group1) ----------
    for (int e = tid; e < 69 * 16; e += NTHREADS) {
        int t = e >> 4, q = e & 15;
        long long node = base - 2 + t;
        bool ok = (node >= 0 && node < (long long)N);
        const float* src = ok ? (x + node * 64 + q * 4) : x;
        CP16(sb + OFF_SH + (uint32_t)(t * 272 + q * 16), src, ok ? 16 : 0);
    }
    CP_COMMIT();                                   // group 0: x
    for (int e = tid; e < 1088; e += NTHREADS)
        CP16(sb + OFF_W1H + e * 16, (const char*)g_W1ph + e * 16, 16);
    for (int e = tid; e < 1088; e += NTHREADS)
        CP16(sb + OFF_W1L + e * 16, (const char*)g_W1pl + e * 16, 16);
    for (int e = tid; e < 256; e += NTHREADS)
        CP16(sb + OFF_BB1 + e * 16, (const char*)g_Bb1 + e * 16, 16);
    for (int e = tid; e < 128; e += NTHREADS)
        CP16(sb + OFF_BB2 + e * 16, (const char*)g_Bb2 + e * 16, 16);
    CP_COMMIT();                                   // group 1: W1 + biases

    if (tid < 72) {
        long long node = base - 2 + tid;
        float v = 0.0f;
        if (tid < 69 && node >= 0 && node < (long long)N)
            v = (node == 0 || node == (long long)N - 1)
                ? 0.70710678118654752f : 0.57735026918962576f;
        sdv[tid] = v;
    }
    sOnes[tid] = __float2half_rn(((tid & 15) < 2) ? 1.0f : 0.0f);

    CP_WAIT(1);          // x landed (group0); W1 may still be in flight
    __syncthreads();

    // ---------- P2: stencil1 (2 rows/thread, float2) -> A1 [80][64] ----------
    for (int e = tid; e < 40 * 32; e += NTHREADS) {
        int rp = e >> 5, kp = (e & 31) * 2;
        int j0 = rp * 2;
        float2 v0 = make_float2(0.f, 0.f), v1 = v0, v2 = v0, v3 = v0;
        if (j0     <= 68) v0 = *(float2*)&sXs[ j0      * LDX + kp];
        if (j0 + 1 <= 68) v1 = *(float2*)&sXs[(j0 + 1) * LDX + kp];
        if (j0 + 2 <= 68) v2 = *(float2*)&sXs[(j0 + 2) * LDX + kp];
        if (j0 + 3 <= 68) v3 = *(float2*)&sXs[(j0 + 3) * LDX + kp];
        #pragma unroll
        for (int rr = 0; rr < 2; rr++) {
            int j = j0 + rr;
            float ax = 0.f, ay = 0.f;
            if (j <= 66) {
                float d0 = sdv[j], d1 = sdv[j + 1], d2 = sdv[j + 2];
                float2 u0 = rr ? v1 : v0, u1 = rr ? v2 : v1, u2 = rr ? v3 : v2;
                ax = d1 * (d0 * u0.x + d1 * u1.x + d2 * u2.x);
                ay = d1 * (d0 * u0.y + d1 * u1.y + d2 * u2.y);
            }
            __half hx, lx, hy, ly;
            split_h(ax, hx, lx);
            split_h(ay, hy, ly);
            *(__half2*)&A1h[j * LDA + kp] = __halves2half2(hx, hy);
            *(__half2*)&A1l[j * LDA + kp] = __halves2half2(lx, ly);
        }
    }
    CP_WAIT(0);          // W1 + biases landed
    __syncthreads();     // A1 visible + copies visible

    // ---------- P3: MMA1  sH = relu(A1 @ W1 + b1) ----------
    {
        const int cg = wid & 3, rg = wid >> 2;
        const int nr = rg ? 2 : 3, s0 = rg * 3;
        wmma::fragment<wmma::matrix_a, 16, 16, 16, __half, wmma::row_major> ah, al;
        wmma::fragment<wmma::matrix_b, 16, 16, 16, __half, wmma::row_major> bh[2], bl[2];
        wmma::fragment<wmma::accumulator, 16, 16, 16, float> acc[3][2];
        #pragma unroll
        for (int r = 0; r < 3; r++)
            #pragma unroll
            for (int c = 0; c < 2; c++) wmma::fill_fragment(acc[r][c], 0.0f);

        // bias init (all operands in smem)
        wmma::load_matrix_sync(ah, sOnes, 16);
        #pragma unroll
        for (int c = 0; c < 2; c++)
            wmma::load_matrix_sync(bh[c], sBb1 + (cg * 2 + c) * 16, 128);
        #pragma unroll
        for (int r = 0; r < 3; r++)
            if (r < nr)
                #pragma unroll
                for (int c = 0; c < 2; c++)
                    wmma::mma_sync(acc[r][c], ah, bh[c], acc[r][c]);

        #pragma unroll
        for (int k = 0; k < 4; k++) {
            #pragma unroll
            for (int c = 0; c < 2; c++) {
                wmma::load_matrix_sync(bh[c], W1h + (k * 16) * LDW1 + (cg * 2 + c) * 16, LDW1);
                wmma::load_matrix_sync(bl[c], W1l + (k * 16) * LDW1 + (cg * 2 + c) * 16, LDW1);
            }
            #pragma unroll
            for (int r = 0; r < 3; r++)
                if (r < nr) {
                    int s = s0 + r;
                    wmma::load_matrix_sync(ah, A1h + (s * 16) * LDA + k * 16, LDA);
                    wmma::load_matrix_sync(al, A1l + (s * 16) * LDA + k * 16, LDA);
                    #pragma unroll
                    for (int c = 0; c < 2; c++) {
                        wmma::mma_sync(acc[r][c], ah, bh[c], acc[r][c]);
                        wmma::mma_sync(acc[r][c], ah, bl[c], acc[r][c]);
                        wmma::mma_sync(acc[r][c], al, bh[c], acc[r][c]);
                    }
                }
        }
        #pragma unroll
        for (int r = 0; r < 3; r++)
            if (r < nr)
                #pragma unroll
                for (int c = 0; c < 2; c++) {
                    #pragma unroll
                    for (int i = 0; i < acc[r][c].num_elements; i++)
                        acc[r][c].x[i] = fmaxf(acc[r][c].x[i], 0.0f);
                    wmma::store_matrix_sync(
                        sH + ((s0 + r) * 16) * LDH + (cg * 2 + c) * 16,
                        acc[r][c], LDH, wmma::mem_row_major);
                }
    }
    __syncthreads();     // sH ready; A1/W1 dead

    // ---------- P4: async W2 stage overlapped with stencil2-chunk0 ----------
    for (int e = tid; e < 1152; e += NTHREADS)
        CP16(sb + OFF_W2H + e * 16, (const char*)g_W2ph + e * 16, 16);
    for (int e = tid; e < 1152; e += NTHREADS)
        CP16(sb + OFF_W2L + e * 16, (const char*)g_W2pl + e * 16, 16);
    CP_COMMIT();

    wmma::fragment<wmma::accumulator, 16, 16, 16, float> acc2[2];
    wmma::fill_fragment(acc2[0], 0.0f);
    wmma::fill_fragment(acc2[1], 0.0f);
    const int c2 = (wid & 3) * 16, rs0 = (wid >> 2) * 2;
    {
        wmma::fragment<wmma::matrix_a, 16, 16, 16, __half, wmma::row_major> aon;
        wmma::fragment<wmma::matrix_b, 16, 16, 16, __half, wmma::row_major> bb;
        wmma::load_matrix_sync(aon, sOnes, 16);
        wmma::load_matrix_sync(bb, sBb2 + c2, 64);
        wmma::mma_sync(acc2[0], aon, bb, acc2[0]);
        wmma::mma_sync(acc2[1], aon, bb, acc2[1]);
    }

    #pragma unroll
    for (int kc = 0; kc < 128; kc += 64) {
        for (int e = tid; e < 32 * 32; e += NTHREADS) {
            int rp = e >> 5, kk = (e & 31) * 2;
            int r0 = rp * 2, k = kc + kk;
            float2 h0 = *(float2*)&sH[ r0      * LDH + k];
            float2 h1 = *(float2*)&sH[(r0 + 1) * LDH + k];
            float2 h2 = *(float2*)&sH[(r0 + 2) * LDH + k];
            float2 h3 = *(float2*)&sH[(r0 + 3) * LDH + k];
            #pragma unroll
            for (int rr = 0; rr < 2; rr++) {
                int r = r0 + rr;
                float d1 = sdv[r + 1], d2 = sdv[r + 2], d3 = sdv[r + 3];
                float2 u0 = rr ? h1 : h0, u1 = rr ? h2 : h1, u2 = rr ? h3 : h2;
                float zx = d2 * (d1 * u0.x + d2 * u1.x + d3 * u2.x);
                float zy = d2 * (d1 * u0.y + d2 * u1.y + d3 * u2.y);
                __half hx, lx, hy, ly;
                split_h(zx, hx, lx);
                split_h(zy, hy, ly);
                *(__half2*)&A2h[r * LDA + kk] = __halves2half2(hx, hy);
                *(__half2*)&A2l[r * LDA + kk] = __halves2half2(lx, ly);
            }
        }
        if (kc == 0) CP_WAIT(0);   // W2 landed before first MMA2 use
        __syncthreads();

        {
            wmma::fragment<wmma::matrix_a, 16, 16, 16, __half, wmma::row_major> ah, al;
            wmma::fragment<wmma::matrix_b, 16, 16, 16, __half, wmma::row_major> bh, bl;
            #pragma unroll
            for (int kk = 0; kk < 4; kk++) {
                wmma::load_matrix_sync(bh, W2h + (kc + kk * 16) * LDW2 + c2, LDW2);
                wmma::load_matrix_sync(bl, W2l + (kc + kk * 16) * LDW2 + c2, LDW2);
                #pragma unroll
                for (int r = 0; r < 2; r++) {
                    wmma::load_matrix_sync(ah, A2h + ((rs0 + r) * 16) * LDA + kk * 16, LDA);
                    wmma::load_matrix_sync(al, A2l + ((rs0 + r) * 16) * LDA + kk * 16, LDA);
                    wmma::mma_sync(acc2[r], ah, bh, acc2[r]);
                    wmma::mma_sync(acc2[r], ah, bl, acc2[r]);
                    wmma::mma_sync(acc2[r], al, bh, acc2[r]);
                }
            }
        }
        __syncthreads();
    }

    // ---------- P5: store (bias already in accumulators) ----------
    if (base + OUT_TILE <= (long long)N) {
        wmma::store_matrix_sync(out + (base + rs0 * 16) * 64 + c2, acc2[0],
                                64, wmma::mem_row_major);
        wmma::store_matrix_sync(out + (base + rs0 * 16 + 16) * 64 + c2, acc2[1],
                                64, wmma::mem_row_major);
    } else {
        wmma::store_matrix_sync(sOut + (rs0 * 16) * LDO + c2, acc2[0], LDO,
                                wmma::mem_row_major);
        wmma::store_matrix_sync(sOut + (rs0 * 16 + 16) * LDO + c2, acc2[1], LDO,
                                wmma::mem_row_major);
        __syncthreads();
        for (int e = tid; e < OUT_TILE * 16; e += NTHREADS) {
            int r = e >> 4, q = e & 15;
            long long node = base + r;
            if (node < (long long)N)
                *(float4*)(out + node * 64 + q * 4) =
                    *(float4*)&sOut[r * LDO + q * 4];
        }
    }
}

extern "C" void kernel_launch(void* const* d_in, const int* in_sizes, int n_in,
                              void* d_out, int out_size)
{
    const float* x  = (const float*)d_in[0];
    const float* W1 = (const float*)d_in[2];
    const float* b1 = (const float*)d_in[3];
    const float* W2 = (const float*)d_in[4];
    const float* b2 = (const float*)d_in[5];
    float* out = (float*)d_out;

    int N = in_sizes[0] / 64;
    int nblocks = (N + OUT_TILE - 1) / OUT_TILE;

    gcn_prep<<<32, 256>>>(W1, b1, W2, b2);

    cudaFuncSetAttribute(gcn_main,
                         cudaFuncAttributeMaxDynamicSharedMemorySize,
                         SMEM_BYTES);
    gcn_main<<<nblocks, NTHREADS, SMEM_BYTES>>>(x, out, N);
}

// round 8
// speedup vs baseline: 1.9165x; 1.0532x over previous
#include <cuda_runtime.h>
#include <cuda_fp16.h>
#include <mma.h>
#include <cstdint>

using namespace nvcuda;

// Fused 2-layer GCN (chain graph), wmma fp16 3-term split.
// R8: persistent 512-thread CTA (1/SM) = two independent 8-warp groups with
//     named barriers (ids 1,2); W1/W2/bias resident in smem (loaded once);
//     per-group tile loop with cross-tile x prefetch via cp.async.

#define NTHREADS 512
#define OUT_TILE 64
#define MROWS    80

#define LDA  72     // fp16: A1 [80][72], A2c [64][72]
#define LDW1 136
#define LDW2 72
#define LDH  132    // fp32 sH [80][132]
#define LDX  68     // fp32 sXs [69][68]
#define LDO  68

// shared (both groups)
#define OFF_W1H 0             // 17408
#define OFF_W1L 17408
#define OFF_W2H 34816         // 18432
#define OFF_W2L 53248
#define OFF_BB1 71680         // 4096
#define OFF_BB2 75776         // 2048
#define OFF_ONES 77824        // 512
#define OFF_GRP  78336
// per-group block (GRP_BYTES):
//  +0     A1h (11520)  [A2h overlay @0, A2l overlay @9216]
//  +11520 A1l (11520)
//  +23040 SH region (42240): sH[80][132] f32; sOut @+0 (17408); sXs @+17408 (18768)
//  +65280 sdv 2 bufs x 384
#define G_A1H  0
#define G_A1L  11520
#define G_A2H  0
#define G_A2L  9216
#define G_SH   23040
#define G_SOUT 23040
#define G_SXS  40448
#define G_SDV  65280
#define GRP_BYTES 66048
#define SMEM_BYTES (OFF_GRP + 2 * GRP_BYTES)   // 210432

__device__ __align__(256) __half g_W1ph[64 * 136];
__device__ __align__(256) __half g_W1pl[64 * 136];
__device__ __align__(256) __half g_W2ph[128 * 72];
__device__ __align__(256) __half g_W2pl[128 * 72];
__device__ __align__(256) __half g_Bb1[16 * 128];
__device__ __align__(256) __half g_Bb2[16 * 64];

__device__ __forceinline__ void split_h(float v, __half& hi, __half& lo) {
    hi = __float2half_rn(v);
    lo = __float2half_rn(v - __half2float(hi));
}
__device__ __forceinline__ uint32_t smem_u32(const void* p) {
    uint32_t a;
    asm("{ .reg .u64 t; cvta.to.shared.u64 t, %1; cvt.u32.u64 %0, t; }"
        : "=r"(a) : "l"(p));
    return a;
}
#define CP16(dst, src, nbytes) \
    asm volatile("cp.async.cg.shared.global [%0], [%1], 16, %2;" \
                 :: "r"(dst), "l"(src), "r"((uint32_t)(nbytes)))
#define CP_COMMIT() asm volatile("cp.async.commit_group;")
#define CP_WAIT0()  asm volatile("cp.async.wait_group 0;")
#define GBAR() asm volatile("bar.sync %0, %1;" :: "r"(grp + 1), "r"(256) : "memory")

__global__ void gcn_prep(const float* __restrict__ W1,
                         const float* __restrict__ b1,
                         const float* __restrict__ W2,
                         const float* __restrict__ b2)
{
    int tid = blockIdx.x * blockDim.x + threadIdx.x;
    int nt = gridDim.x * blockDim.x;
    for (int e = tid; e < 64 * 136; e += nt) {
        int r = e / 136, c = e % 136;
        __half hi = __float2half_rn(0.f), lo = hi;
        if (c < 128) split_h(W1[r * 128 + c], hi, lo);
        g_W1ph[e] = hi; g_W1pl[e] = lo;
    }
    for (int e = tid; e < 128 * 72; e += nt) {
        int r = e / 72, c = e % 72;
        __half hi = __float2half_rn(0.f), lo = hi;
        if (c < 64) split_h(W2[r * 64 + c], hi, lo);
        g_W2ph[e] = hi; g_W2pl[e] = lo;
    }
    for (int e = tid; e < 16 * 128; e += nt) {
        int r = e >> 7, c = e & 127;
        __half hi, lo; split_h(b1[c], hi, lo);
        g_Bb1[e] = (r == 0) ? hi : (r == 1) ? lo : __float2half_rn(0.f);
    }
    for (int e = tid; e < 16 * 64; e += nt) {
        int r = e >> 6, c = e & 63;
        __half hi, lo; split_h(b2[c], hi, lo);
        g_Bb2[e] = (r == 0) ? hi : (r == 1) ? lo : __float2half_rn(0.f);
    }
}

__global__ __launch_bounds__(NTHREADS, 1)
void gcn_main(const float* __restrict__ x, float* __restrict__ out, int N)
{
    extern __shared__ char smem[];
    const uint32_t sb = smem_u32(smem);
    const int tid = threadIdx.x;
    const int grp = tid >> 8;          // 0 or 1
    const int gtid = tid & 255;
    const int gwid = gtid >> 5;

    // ---------- one-time: stage W1/W2/biases (all 512 threads) ----------
    for (int e = tid; e < 1088; e += NTHREADS)
        CP16(sb + OFF_W1H + e * 16, (const char*)g_W1ph + e * 16, 16);
    for (int e = tid; e < 1088; e += NTHREADS)
        CP16(sb + OFF_W1L + e * 16, (const char*)g_W1pl + e * 16, 16);
    for (int e = tid; e < 1152; e += NTHREADS)
        CP16(sb + OFF_W2H + e * 16, (const char*)g_W2ph + e * 16, 16);
    for (int e = tid; e < 1152; e += NTHREADS)
        CP16(sb + OFF_W2L + e * 16, (const char*)g_W2pl + e * 16, 16);
    for (int e = tid; e < 256; e += NTHREADS)
        CP16(sb + OFF_BB1 + e * 16, (const char*)g_Bb1 + e * 16, 16);
    for (int e = tid; e < 128; e += NTHREADS)
        CP16(sb + OFF_BB2 + e * 16, (const char*)g_Bb2 + e * 16, 16);
    CP_COMMIT();
    if (tid < 256)
        ((__half*)(smem + OFF_ONES))[tid] =
            __float2half_rn(((tid & 15) < 2) ? 1.0f : 0.0f);

    __half* W1h = (__half*)(smem + OFF_W1H);
    __half* W1l = (__half*)(smem + OFF_W1L);
    __half* W2h = (__half*)(smem + OFF_W2H);
    __half* W2l = (__half*)(smem + OFF_W2L);
    __half* sBb1 = (__half*)(smem + OFF_BB1);
    __half* sBb2 = (__half*)(smem + OFF_BB2);
    __half* sOnes = (__half*)(smem + OFF_ONES);

    char* gbp = smem + OFF_GRP + grp * GRP_BYTES;
    const uint32_t gb = sb + OFF_GRP + grp * GRP_BYTES;
    __half* A1h = (__half*)(gbp + G_A1H);
    __half* A1l = (__half*)(gbp + G_A1L);
    __half* A2h = (__half*)(gbp + G_A2H);
    __half* A2l = (__half*)(gbp + G_A2L);
    float* sH   = (float*)(gbp + G_SH);
    float* sOut = (float*)(gbp + G_SOUT);
    float* sXs  = (float*)(gbp + G_SXS);

    const long long ntiles = ((long long)N + OUT_TILE - 1) / OUT_TILE;
    const long long stride = (long long)gridDim.x * 2;
    long long tile = (long long)blockIdx.x * 2 + grp;
    int p = 0;

    // ---------- prologue: first tile's x + dinv ----------
    if (tile < ntiles) {
        long long base = tile * OUT_TILE;
        for (int e = gtid; e < 69 * 16; e += 256) {
            int t = e >> 4, q = e & 15;
            long long node = base - 2 + t;
            bool ok = (node >= 0 && node < (long long)N);
            const float* src = ok ? (x + node * 64 + q * 4) : x;
            CP16(gb + G_SXS + (uint32_t)(t * 272 + q * 16), src, ok ? 16 : 0);
        }
        if (gtid < 72) {
            long long node = base - 2 + gtid;
            float v = 0.0f;
            if (gtid < 69 && node >= 0 && node < (long long)N)
                v = (node == 0 || node == (long long)N - 1)
                    ? 0.70710678118654752f : 0.57735026918962576f;
            ((float*)(gbp + G_SDV))[gtid] = v;
        }
    }
    CP_COMMIT();
    CP_WAIT0();
    __syncthreads();    // W + first x visible to everyone

    // ---------- per-group persistent tile loop ----------
    for (; tile < ntiles; tile += stride) {
        const long long base = tile * OUT_TILE;
        float* sdv = (float*)(gbp + G_SDV + p * 384);

        // ---- stencil1 (2 rows/thread, float2) -> A1 [80][64] ----
        for (int e = gtid; e < 40 * 32; e += 256) {
            int rp = e >> 5, kp = (e & 31) * 2;
            int j0 = rp * 2;
            float2 v0 = make_float2(0.f, 0.f), v1 = v0, v2 = v0, v3 = v0;
            if (j0     <= 68) v0 = *(float2*)&sXs[ j0      * LDX + kp];
            if (j0 + 1 <= 68) v1 = *(float2*)&sXs[(j0 + 1) * LDX + kp];
            if (j0 + 2 <= 68) v2 = *(float2*)&sXs[(j0 + 2) * LDX + kp];
            if (j0 + 3 <= 68) v3 = *(float2*)&sXs[(j0 + 3) * LDX + kp];
            #pragma unroll
            for (int rr = 0; rr < 2; rr++) {
                int j = j0 + rr;
                float ax = 0.f, ay = 0.f;
                if (j <= 66) {
                    float d0 = sdv[j], d1 = sdv[j + 1], d2 = sdv[j + 2];
                    float2 u0 = rr ? v1 : v0, u1 = rr ? v2 : v1, u2 = rr ? v3 : v2;
                    ax = d1 * (d0 * u0.x + d1 * u1.x + d2 * u2.x);
                    ay = d1 * (d0 * u0.y + d1 * u1.y + d2 * u2.y);
                }
                __half hx, lx, hy, ly;
                split_h(ax, hx, lx);
                split_h(ay, hy, ly);
                *(__half2*)&A1h[j * LDA + kp] = __halves2half2(hx, hy);
                *(__half2*)&A1l[j * LDA + kp] = __halves2half2(lx, ly);
            }
        }
        GBAR();

        // ---- MMA1: sH = relu(A1 @ W1 + b1) ----
        {
            const int cg = gwid & 3, rg = gwid >> 2;
            const int nr = rg ? 2 : 3, s0 = rg * 3;
            wmma::fragment<wmma::matrix_a, 16, 16, 16, __half, wmma::row_major> ah, al;
            wmma::fragment<wmma::matrix_b, 16, 16, 16, __half, wmma::row_major> bh[2], bl[2];
            wmma::fragment<wmma::accumulator, 16, 16, 16, float> acc[3][2];
            #pragma unroll
            for (int r = 0; r < 3; r++)
                #pragma unroll
                for (int c = 0; c < 2; c++) wmma::fill_fragment(acc[r][c], 0.0f);

            wmma::load_matrix_sync(ah, sOnes, 16);
            #pragma unroll
            for (int c = 0; c < 2; c++)
                wmma::load_matrix_sync(bh[c], sBb1 + (cg * 2 + c) * 16, 128);
            #pragma unroll
            for (int r = 0; r < 3; r++)
                if (r < nr)
                    #pragma unroll
                    for (int c = 0; c < 2; c++)
                        wmma::mma_sync(acc[r][c], ah, bh[c], acc[r][c]);

            #pragma unroll
            for (int k = 0; k < 4; k++) {
                #pragma unroll
                for (int c = 0; c < 2; c++) {
                    wmma::load_matrix_sync(bh[c], W1h + (k * 16) * LDW1 + (cg * 2 + c) * 16, LDW1);
                    wmma::load_matrix_sync(bl[c], W1l + (k * 16) * LDW1 + (cg * 2 + c) * 16, LDW1);
                }
                #pragma unroll
                for (int r = 0; r < 3; r++)
                    if (r < nr) {
                        int s = s0 + r;
                        wmma::load_matrix_sync(ah, A1h + (s * 16) * LDA + k * 16, LDA);
                        wmma::load_matrix_sync(al, A1l + (s * 16) * LDA + k * 16, LDA);
                        #pragma unroll
                        for (int c = 0; c < 2; c++) {
                            wmma::mma_sync(acc[r][c], ah, bh[c], acc[r][c]);
                            wmma::mma_sync(acc[r][c], ah, bl[c], acc[r][c]);
                            wmma::mma_sync(acc[r][c], al, bh[c], acc[r][c]);
                        }
                    }
            }
            #pragma unroll
            for (int r = 0; r < 3; r++)
                if (r < nr)
                    #pragma unroll
                    for (int c = 0; c < 2; c++) {
                        #pragma unroll
                        for (int i = 0; i < acc[r][c].num_elements; i++)
                            acc[r][c].x[i] = fmaxf(acc[r][c].x[i], 0.0f);
                        wmma::store_matrix_sync(
                            sH + ((s0 + r) * 16) * LDH + (cg * 2 + c) * 16,
                            acc[r][c], LDH, wmma::mem_row_major);
                    }
        }
        GBAR();

        // ---- K-chunked stencil2 + MMA2 (W2 resident) ----
        wmma::fragment<wmma::accumulator, 16, 16, 16, float> acc2[2];
        wmma::fill_fragment(acc2[0], 0.0f);
        wmma::fill_fragment(acc2[1], 0.0f);
        const int c2 = (gwid & 3) * 16, rs0 = (gwid >> 2) * 2;
        {
            wmma::fragment<wmma::matrix_a, 16, 16, 16, __half, wmma::row_major> aon;
            wmma::fragment<wmma::matrix_b, 16, 16, 16, __half, wmma::row_major> bb;
            wmma::load_matrix_sync(aon, sOnes, 16);
            wmma::load_matrix_sync(bb, sBb2 + c2, 64);
            wmma::mma_sync(acc2[0], aon, bb, acc2[0]);
            wmma::mma_sync(acc2[1], aon, bb, acc2[1]);
        }

        #pragma unroll
        for (int kc = 0; kc < 128; kc += 64) {
            for (int e = gtid; e < 32 * 32; e += 256) {
                int rp = e >> 5, kk = (e & 31) * 2;
                int r0 = rp * 2, k = kc + kk;
                float2 h0 = *(float2*)&sH[ r0      * LDH + k];
                float2 h1 = *(float2*)&sH[(r0 + 1) * LDH + k];
                float2 h2 = *(float2*)&sH[(r0 + 2) * LDH + k];
                float2 h3 = *(float2*)&sH[(r0 + 3) * LDH + k];
                #pragma unroll
                for (int rr = 0; rr < 2; rr++) {
                    int r = r0 + rr;
                    float d1 = sdv[r + 1], d2 = sdv[r + 2], d3 = sdv[r + 3];
                    float2 u0 = rr ? h1 : h0, u1 = rr ? h2 : h1, u2 = rr ? h3 : h2;
                    float zx = d2 * (d1 * u0.x + d2 * u1.x + d3 * u2.x);
                    float zy = d2 * (d1 * u0.y + d2 * u1.y + d3 * u2.y);
                    __half hx, lx, hy, ly;
                    split_h(zx, hx, lx);
                    split_h(zy, hy, ly);
                    *(__half2*)&A2h[r * LDA + kk] = __halves2half2(hx, hy);
                    *(__half2*)&A2l[r * LDA + kk] = __halves2half2(lx, ly);
                }
            }
            GBAR();   // A2 chunk ready; (kc=64) sH reads done -> prefetch may land

            if (kc == 64) {
                // ---- cross-tile prefetch: next x + dinv (overlaps MMA2 c1) ----
                long long nt = tile + stride;
                if (nt < ntiles) {
                    long long nbase = nt * OUT_TILE;
                    for (int e = gtid; e < 69 * 16; e += 256) {
                        int t = e >> 4, q = e & 15;
                        long long node = nbase - 2 + t;
                        bool ok = (node >= 0 && node < (long long)N);
                        const float* src = ok ? (x + node * 64 + q * 4) : x;
                        CP16(gb + G_SXS + (uint32_t)(t * 272 + q * 16), src,
                             ok ? 16 : 0);
                    }
                    if (gtid < 72) {
                        long long node = nbase - 2 + gtid;
                        float v = 0.0f;
                        if (gtid < 69 && node >= 0 && node < (long long)N)
                            v = (node == 0 || node == (long long)N - 1)
                                ? 0.70710678118654752f : 0.57735026918962576f;
                        ((float*)(gbp + G_SDV + (p ^ 1) * 384))[gtid] = v;
                    }
                }
                CP_COMMIT();
            }

            {
                wmma::fragment<wmma::matrix_a, 16, 16, 16, __half, wmma::row_major> ah, al;
                wmma::fragment<wmma::matrix_b, 16, 16, 16, __half, wmma::row_major> bh, bl;
                #pragma unroll
                for (int kk = 0; kk < 4; kk++) {
                    wmma::load_matrix_sync(bh, W2h + (kc + kk * 16) * LDW2 + c2, LDW2);
                    wmma::load_matrix_sync(bl, W2l + (kc + kk * 16) * LDW2 + c2, LDW2);
                    #pragma unroll
                    for (int r = 0; r < 2; r++) {
                        wmma::load_matrix_sync(ah, A2h + ((rs0 + r) * 16) * LDA + kk * 16, LDA);
                        wmma::load_matrix_sync(al, A2l + ((rs0 + r) * 16) * LDA + kk * 16, LDA);
                        wmma::mma_sync(acc2[r], ah, bh, acc2[r]);
                        wmma::mma_sync(acc2[r], ah, bl, acc2[r]);
                        wmma::mma_sync(acc2[r], al, bh, acc2[r]);
                    }
                }
            }
            if (kc == 64) CP_WAIT0();
            GBAR();
        }

        // ---- store (bias already inside accumulators) ----
        if (base + OUT_TILE <= (long long)N) {
            wmma::store_matrix_sync(out + (base + rs0 * 16) * 64 + c2, acc2[0],
                                    64, wmma::mem_row_major);
            wmma::store_matrix_sync(out + (base + rs0 * 16 + 16) * 64 + c2, acc2[1],
                                    64, wmma::mem_row_major);
        } else {
            wmma::store_matrix_sync(sOut + (rs0 * 16) * LDO + c2, acc2[0], LDO,
                                    wmma::mem_row_major);
            wmma::store_matrix_sync(sOut + (rs0 * 16 + 16) * LDO + c2, acc2[1], LDO,
                                    wmma::mem_row_major);
            GBAR();
            for (int e = gtid; e < OUT_TILE * 16; e += 256) {
                int r = e >> 4, q = e & 15;
                long long node = base + r;
                if (node < (long long)N)
                    *(float4*)(out + node * 64 + q * 4) =
                        *(float4*)&sOut[r * LDO + q * 4];
            }
        }
        p ^= 1;
    }
}

extern "C" void kernel_launch(void* const* d_in, const int* in_sizes, int n_in,
                              void* d_out, int out_size)
{
    const float* x  = (const float*)d_in[0];
    const float* W1 = (const float*)d_in[2];
    const float* b1 = (const float*)d_in[3];
    const float* W2 = (const float*)d_in[4];
    const float* b2 = (const float*)d_in[5];
    float* out = (float*)d_out;

    int N = in_sizes[0] / 64;

    int dev = 0, sms = 148;
    cudaGetDevice(&dev);
    cudaDeviceGetAttribute(&sms, cudaDevAttrMultiProcessorCount, dev);

    gcn_prep<<<32, 256>>>(W1, b1, W2, b2);

    cudaFuncSetAttribute(gcn_main,
                         cudaFuncAttributeMaxDynamicSharedMemorySize,
                         SMEM_BYTES);
    gcn_main<<<sms, NTHREADS, SMEM_BYTES>>>(x, out, N);
}

// round 9
// speedup vs baseline: 2.0229x; 1.0555x over previous
#include <cuda_runtime.h>
#include <cuda_fp16.h>
#include <mma.h>
#include <cstdint>

using namespace nvcuda;

// Fused 2-layer GCN (chain graph), wmma fp16 3-term split.
// R9: persistent 512-thread CTA = two 8-warp groups (named barriers);
//     OUT_TILE=62 -> layer-1 halo fits exactly 64 MMA rows (waste 1.25->1.03);
//     stencil2/MMA2 chunk pipeline (32-col chunks, double-buffered A2);
//     dedicated sXs buffer -> early long-range x prefetch; 4-row stencils.

#define NTHREADS 512
#define OUT_TILE 62
#define XROWS    66     // x halo rows: nodes base-2 .. base+63
#define HROWS    64     // MMA1 rows: h nodes base-1 .. base+62

#define LDA1  72    // halfs (144B, 16B-mult)
#define LDW1  136
#define LDW2  72
#define LDH   130   // fp32
#define LDX   68    // fp32 (272B rows)
#define LDA2C 40    // halfs per chunk row (80B)
#define LDO   68

// shared (both groups)
#define OFF_W1H 0
#define OFF_W1L 17408
#define OFF_W2H 34816
#define OFF_W2L 53248
#define OFF_BB1 71680
#define OFF_BB2 75776
#define OFF_ONES 77824
#define OFF_GRP  78336
// per-group block:
#define G_A    0        // 20480: A1h@0(9216) A1l@9216 ; A2 buf0@0(h0,l@5120) buf1@10240
#define G_SH   20480    // 33280: sH[64][130] f32 ; sOut overlays @G_SH
#define G_SXS  53760    // 17952: sXs[66][68] f32 (dedicated)
#define G_SDV  71712    // 2 x 288
#define GRP_BYTES 72288
#define SMEM_BYTES (OFF_GRP + 2 * GRP_BYTES)   // 222912

__device__ __align__(256) __half g_W1ph[64 * 136];
__device__ __align__(256) __half g_W1pl[64 * 136];
__device__ __align__(256) __half g_W2ph[128 * 72];
__device__ __align__(256) __half g_W2pl[128 * 72];
__device__ __align__(256) __half g_Bb1[16 * 128];
__device__ __align__(256) __half g_Bb2[16 * 64];

__device__ __forceinline__ void split_h(float v, __half& hi, __half& lo) {
    hi = __float2half_rn(v);
    lo = __float2half_rn(v - __half2float(hi));
}
__device__ __forceinline__ uint32_t smem_u32(const void* p) {
    uint32_t a;
    asm("{ .reg .u64 t; cvta.to.shared.u64 t, %1; cvt.u32.u64 %0, t; }"
        : "=r"(a) : "l"(p));
    return a;
}
#define CP16(dst, src, nbytes) \
    asm volatile("cp.async.cg.shared.global [%0], [%1], 16, %2;" \
                 :: "r"(dst), "l"(src), "r"((uint32_t)(nbytes)))
#define CP_COMMIT() asm volatile("cp.async.commit_group;")
#define CP_WAIT0()  asm volatile("cp.async.wait_group 0;")
#define GBAR() asm volatile("bar.sync %0, %1;" :: "r"(grp + 1), "r"(256) : "memory")

__global__ void gcn_prep(const float* __restrict__ W1,
                         const float* __restrict__ b1,
                         const float* __restrict__ W2,
                         const float* __restrict__ b2)
{
    int tid = blockIdx.x * blockDim.x + threadIdx.x;
    int nt = gridDim.x * blockDim.x;
    for (int e = tid; e < 64 * 136; e += nt) {
        int r = e / 136, c = e % 136;
        __half hi = __float2half_rn(0.f), lo = hi;
        if (c < 128) split_h(W1[r * 128 + c], hi, lo);
        g_W1ph[e] = hi; g_W1pl[e] = lo;
    }
    for (int e = tid; e < 128 * 72; e += nt) {
        int r = e / 72, c = e % 72;
        __half hi = __float2half_rn(0.f), lo = hi;
        if (c < 64) split_h(W2[r * 64 + c], hi, lo);
        g_W2ph[e] = hi; g_W2pl[e] = lo;
    }
    for (int e = tid; e < 16 * 128; e += nt) {
        int r = e >> 7, c = e & 127;
        __half hi, lo; split_h(b1[c], hi, lo);
        g_Bb1[e] = (r == 0) ? hi : (r == 1) ? lo : __float2half_rn(0.f);
    }
    for (int e = tid; e < 16 * 64; e += nt) {
        int r = e >> 6, c = e & 63;
        __half hi, lo; split_h(b2[c], hi, lo);
        g_Bb2[e] = (r == 0) ? hi : (r == 1) ? lo : __float2half_rn(0.f);
    }
}

__global__ __launch_bounds__(NTHREADS, 1)
void gcn_main(const float* __restrict__ x, float* __restrict__ out, int N)
{
    extern __shared__ char smem[];
    const uint32_t sb = smem_u32(smem);
    const int tid = threadIdx.x;
    const int grp = tid >> 8;
    const int gtid = tid & 255;
    const int gwid = gtid >> 5;

    // ---------- one-time: stage W / biases ----------
    for (int e = tid; e < 1088; e += NTHREADS)
        CP16(sb + OFF_W1H + e * 16, (const char*)g_W1ph + e * 16, 16);
    for (int e = tid; e < 1088; e += NTHREADS)
        CP16(sb + OFF_W1L + e * 16, (const char*)g_W1pl + e * 16, 16);
    for (int e = tid; e < 1152; e += NTHREADS)
        CP16(sb + OFF_W2H + e * 16, (const char*)g_W2ph + e * 16, 16);
    for (int e = tid; e < 1152; e += NTHREADS)
        CP16(sb + OFF_W2L + e * 16, (const char*)g_W2pl + e * 16, 16);
    for (int e = tid; e < 256; e += NTHREADS)
        CP16(sb + OFF_BB1 + e * 16, (const char*)g_Bb1 + e * 16, 16);
    for (int e = tid; e < 128; e += NTHREADS)
        CP16(sb + OFF_BB2 + e * 16, (const char*)g_Bb2 + e * 16, 16);
    if (tid < 256)
        ((__half*)(smem + OFF_ONES))[tid] =
            __float2half_rn(((tid & 15) < 2) ? 1.0f : 0.0f);

    __half* W1h = (__half*)(smem + OFF_W1H);
    __half* W1l = (__half*)(smem + OFF_W1L);
    __half* W2h = (__half*)(smem + OFF_W2H);
    __half* W2l = (__half*)(smem + OFF_W2L);
    __half* sBb1 = (__half*)(smem + OFF_BB1);
    __half* sBb2 = (__half*)(smem + OFF_BB2);
    __half* sOnes = (__half*)(smem + OFF_ONES);

    char* gbp = smem + OFF_GRP + grp * GRP_BYTES;
    const uint32_t gb = sb + OFF_GRP + grp * GRP_BYTES;
    __half* A1h = (__half*)(gbp + G_A);
    __half* A1l = (__half*)(gbp + G_A + 9216);
    float* sH   = (float*)(gbp + G_SH);
    float* sOut = (float*)(gbp + G_SH);      // staging (full: 16 rows; edge: 64)
    float* sXs  = (float*)(gbp + G_SXS);

    const long long ntiles = ((long long)N + OUT_TILE - 1) / OUT_TILE;
    const long long stride = (long long)gridDim.x * 2;
    long long tile = (long long)blockIdx.x * 2 + grp;
    int p = 0;

    // ---------- prologue: first tile's x + dinv ----------
    if (tile < ntiles) {
        long long base = tile * OUT_TILE;
        for (int e = gtid; e < XROWS * 16; e += 256) {
            int t = e >> 4, q = e & 15;
            long long node = base - 2 + t;
            bool ok = (node >= 0 && node < (long long)N);
            const float* src = ok ? (x + node * 64 + q * 4) : x;
            CP16(gb + G_SXS + (uint32_t)(t * 272 + q * 16), src, ok ? 16 : 0);
        }
        if (gtid < 68) {
            long long node = base - 2 + gtid;
            float v = 0.0f;
            if (node >= 0 && node < (long long)N)
                v = (node == 0 || node == (long long)N - 1)
                    ? 0.70710678118654752f : 0.57735026918962576f;
            ((float*)(gbp + G_SDV))[gtid] = v;
        }
    }
    CP_COMMIT();
    CP_WAIT0();
    __syncthreads();

    // ---------- persistent tile loop ----------
    for (; tile < ntiles; tile += stride) {
        const long long base = tile * OUT_TILE;
        float* sdv = (float*)(gbp + G_SDV + p * 288);

        // ---- stencil1 (4 rows/task) -> A1 [64][64] ----
        // row j -> h node base-1+j ; reads x rows j..j+2 ; dinv idx j..j+2
        for (int e = gtid; e < 16 * 32; e += 256) {
            int j0 = (e >> 5) * 4, kp = (e & 31) * 2;
            float2 v[6];
            #pragma unroll
            for (int i = 0; i < 6; i++)          // j0+5 <= 65 always valid
                v[i] = *(float2*)&sXs[(j0 + i) * LDX + kp];
            #pragma unroll
            for (int rr = 0; rr < 4; rr++) {
                int j = j0 + rr;
                float d0 = sdv[j], d1 = sdv[j + 1], d2 = sdv[j + 2];
                float ax = d1 * (d0 * v[rr].x + d1 * v[rr + 1].x + d2 * v[rr + 2].x);
                float ay = d1 * (d0 * v[rr].y + d1 * v[rr + 1].y + d2 * v[rr + 2].y);
                __half hx, lx, hy, ly;
                split_h(ax, hx, lx);
                split_h(ay, hy, ly);
                *(__half2*)&A1h[j * LDA1 + kp] = __halves2half2(hx, hy);
                *(__half2*)&A1l[j * LDA1 + kp] = __halves2half2(lx, ly);
            }
        }
        GBAR();

        // ---- prefetch next tile's x + dinv (lands any time before loop end) ----
        {
            long long nt2 = tile + stride;
            if (nt2 < ntiles) {
                long long nbase = nt2 * OUT_TILE;
                for (int e = gtid; e < XROWS * 16; e += 256) {
                    int t = e >> 4, q = e & 15;
                    long long node = nbase - 2 + t;
                    bool ok = (node >= 0 && node < (long long)N);
                    const float* src = ok ? (x + node * 64 + q * 4) : x;
                    CP16(gb + G_SXS + (uint32_t)(t * 272 + q * 16), src, ok ? 16 : 0);
                }
                if (gtid < 68) {
                    long long node = nbase - 2 + gtid;
                    float v = 0.0f;
                    if (node >= 0 && node < (long long)N)
                        v = (node == 0 || node == (long long)N - 1)
                            ? 0.70710678118654752f : 0.57735026918962576f;
                    ((float*)(gbp + G_SDV + (p ^ 1) * 288))[gtid] = v;
                }
            }
            CP_COMMIT();
        }

        // ---- MMA1: sH[64][128] = relu(A1 @ W1 + b1) ; warp = 2x2 slabs ----
        {
            const int cg = gwid & 3, rg = gwid >> 2;
            wmma::fragment<wmma::matrix_a, 16, 16, 16, __half, wmma::row_major> ah, al;
            wmma::fragment<wmma::matrix_b, 16, 16, 16, __half, wmma::row_major> bh[2], bl[2];
            wmma::fragment<wmma::accumulator, 16, 16, 16, float> acc[2][2];
            #pragma unroll
            for (int r = 0; r < 2; r++)
                #pragma unroll
                for (int c = 0; c < 2; c++) wmma::fill_fragment(acc[r][c], 0.0f);

            wmma::load_matrix_sync(ah, sOnes, 16);
            #pragma unroll
            for (int c = 0; c < 2; c++)
                wmma::load_matrix_sync(bh[c], sBb1 + (cg * 2 + c) * 16, 128);
            #pragma unroll
            for (int r = 0; r < 2; r++)
                #pragma unroll
                for (int c = 0; c < 2; c++)
                    wmma::mma_sync(acc[r][c], ah, bh[c], acc[r][c]);

            #pragma unroll
            for (int k = 0; k < 4; k++) {
                #pragma unroll
                for (int c = 0; c < 2; c++) {
                    wmma::load_matrix_sync(bh[c], W1h + (k * 16) * LDW1 + (cg * 2 + c) * 16, LDW1);
                    wmma::load_matrix_sync(bl[c], W1l + (k * 16) * LDW1 + (cg * 2 + c) * 16, LDW1);
                }
                #pragma unroll
                for (int r = 0; r < 2; r++) {
                    wmma::load_matrix_sync(ah, A1h + ((rg * 2 + r) * 16) * LDA1 + k * 16, LDA1);
                    wmma::load_matrix_sync(al, A1l + ((rg * 2 + r) * 16) * LDA1 + k * 16, LDA1);
                    #pragma unroll
                    for (int c = 0; c < 2; c++) {
                        wmma::mma_sync(acc[r][c], ah, bh[c], acc[r][c]);
                        wmma::mma_sync(acc[r][c], ah, bl[c], acc[r][c]);
                        wmma::mma_sync(acc[r][c], al, bh[c], acc[r][c]);
                    }
                }
            }
            #pragma unroll
            for (int r = 0; r < 2; r++)
                #pragma unroll
                for (int c = 0; c < 2; c++) {
                    #pragma unroll
                    for (int i = 0; i < acc[r][c].num_elements; i++)
                        acc[r][c].x[i] = fmaxf(acc[r][c].x[i], 0.0f);
                    wmma::store_matrix_sync(
                        sH + ((rg * 2 + r) * 16) * LDH + (cg * 2 + c) * 16,
                        acc[r][c], LDH, wmma::mem_row_major);
                }
        }
        GBAR();          // sH ready; A1 dead (A2 buffers may overwrite)

        // ---- stencil2 chunk helper (inlined twice below via lambda) ----
        auto stencil2_chunk = [&](int c, int b) {
            __half* bufh = (__half*)(gbp + G_A + b * 10240);
            __half* bufl = (__half*)(gbp + G_A + b * 10240 + 5120);
            int kc = c * 32;
            int r0 = (gtid >> 4) * 4, kp = (gtid & 15) * 2;
            float2 v[6];
            #pragma unroll
            for (int i = 0; i < 6; i++)
                v[i] = (r0 + i <= 63) ? *(float2*)&sH[(r0 + i) * LDH + kc + kp]
                                      : make_float2(0.f, 0.f);
            #pragma unroll
            for (int rr = 0; rr < 4; rr++) {
                int r = r0 + rr;
                float zx = 0.f, zy = 0.f;
                if (r <= 61) {
                    float d1 = sdv[r + 1], d2 = sdv[r + 2], d3 = sdv[r + 3];
                    zx = d2 * (d1 * v[rr].x + d2 * v[rr + 1].x + d3 * v[rr + 2].x);
                    zy = d2 * (d1 * v[rr].y + d2 * v[rr + 1].y + d3 * v[rr + 2].y);
                }
                __half hx, lx, hy, ly;
                split_h(zx, hx, lx);
                split_h(zy, hy, ly);
                *(__half2*)&bufh[r * LDA2C + kp] = __halves2half2(hx, hy);
                *(__half2*)&bufl[r * LDA2C + kp] = __halves2half2(lx, ly);
            }
        };

        // ---- chunk-pipelined stencil2 / MMA2 ----
        wmma::fragment<wmma::accumulator, 16, 16, 16, float> acc2[2];
        wmma::fill_fragment(acc2[0], 0.0f);
        wmma::fill_fragment(acc2[1], 0.0f);
        const int c2 = (gwid & 3) * 16, rs0 = (gwid >> 2) * 2;
        {
            wmma::fragment<wmma::matrix_a, 16, 16, 16, __half, wmma::row_major> aon;
            wmma::fragment<wmma::matrix_b, 16, 16, 16, __half, wmma::row_major> bb;
            wmma::load_matrix_sync(aon, sOnes, 16);
            wmma::load_matrix_sync(bb, sBb2 + c2, 64);
            wmma::mma_sync(acc2[0], aon, bb, acc2[0]);
            wmma::mma_sync(acc2[1], aon, bb, acc2[1]);
        }

        stencil2_chunk(0, 0);
        GBAR();

        #pragma unroll
        for (int c = 0; c < 4; c++) {
            if (c < 3) stencil2_chunk(c + 1, (c + 1) & 1);
            {
                __half* bufh = (__half*)(gbp + G_A + (c & 1) * 10240);
                __half* bufl = (__half*)(gbp + G_A + (c & 1) * 10240 + 5120);
                wmma::fragment<wmma::matrix_a, 16, 16, 16, __half, wmma::row_major> ah, al;
                wmma::fragment<wmma::matrix_b, 16, 16, 16, __half, wmma::row_major> bh, bl;
                #pragma unroll
                for (int s = 0; s < 2; s++) {
                    wmma::load_matrix_sync(bh, W2h + (c * 32 + s * 16) * LDW2 + c2, LDW2);
                    wmma::load_matrix_sync(bl, W2l + (c * 32 + s * 16) * LDW2 + c2, LDW2);
                    #pragma unroll
                    for (int r = 0; r < 2; r++) {
                        wmma::load_matrix_sync(ah, bufh + ((rs0 + r) * 16) * LDA2C + s * 16, LDA2C);
                        wmma::load_matrix_sync(al, bufl + ((rs0 + r) * 16) * LDA2C + s * 16, LDA2C);
                        wmma::mma_sync(acc2[r], ah, bh, acc2[r]);
                        wmma::mma_sync(acc2[r], ah, bl, acc2[r]);
                        wmma::mma_sync(acc2[r], al, bh, acc2[r]);
                    }
                }
            }
            if (c == 3) CP_WAIT0();      // next-tile x landed
            GBAR();
        }

        // ---- store: rows 0..47 direct; rows 48..61 staged (slab 3) ----
        if (base + OUT_TILE <= (long long)N) {
            #pragma unroll
            for (int r = 0; r < 2; r++) {
                int row0 = (rs0 + r) * 16;
                if (row0 < 48)
                    wmma::store_matrix_sync(out + (base + row0) * 64 + c2,
                                            acc2[r], 64, wmma::mem_row_major);
                else
                    wmma::store_matrix_sync(sOut + 0 * LDO + c2, acc2[r], LDO,
                                            wmma::mem_row_major);
            }
            GBAR();
            for (int e = gtid; e < 14 * 16; e += 256) {
                int r = e >> 4, q = e & 15;
                *(float4*)(out + (base + 48 + r) * 64 + q * 4) =
                    *(float4*)&sOut[r * LDO + q * 4];
            }
        } else {
            // edge tile: stage all 64 rows, guarded copy
            wmma::store_matrix_sync(sOut + (rs0 * 16) * LDO + c2, acc2[0], LDO,
                                    wmma::mem_row_major);
            wmma::store_matrix_sync(sOut + ((rs0 + 1) * 16) * LDO + c2, acc2[1], LDO,
                                    wmma::mem_row_major);
            GBAR();
            for (int e = gtid; e < 62 * 16; e += 256) {
                int r = e >> 4, q = e & 15;
                long long node = base + r;
                if (node < (long long)N)
                    *(float4*)(out + node * 64 + q * 4) =
                        *(float4*)&sOut[r * LDO + q * 4];
            }
        }
        p ^= 1;
    }
}

extern "C" void kernel_launch(void* const* d_in, const int* in_sizes, int n_in,
                              void* d_out, int out_size)
{
    const float* x  = (const float*)d_in[0];
    const float* W1 = (const float*)d_in[2];
    const float* b1 = (const float*)d_in[3];
    const float* W2 = (const float*)d_in[4];
    const float* b2 = (const float*)d_in[5];
    float* out = (float*)d_out;

    int N = in_sizes[0] / 64;

    int dev = 0, sms = 148;
    cudaGetDevice(&dev);
    cudaDeviceGetAttribute(&sms, cudaDevAttrMultiProcessorCount, dev);

    gcn_prep<<<32, 256>>>(W1, b1, W2, b2);

    cudaFuncSetAttribute(gcn_main,
                         cudaFuncAttributeMaxDynamicSharedMemorySize,
                         SMEM_BYTES);
    gcn_main<<<sms, NTHREADS, SMEM_BYTES>>>(x, out, N);
}